// round 4
// baseline (speedup 1.0000x reference)
#include <cuda_runtime.h>
#include <cstdint>

#define NMAX 100000
#define EMAX 1600000
#define DIN 128

// ---------------- device scratch ----------------
__device__ int   g_deg[NMAX];
__device__ int   g_rowptr[NMAX + 1];
__device__ int   g_cursor[NMAX];
__device__ int   g_adj[EMAX];
__device__ float g_deginv[NMAX];
__device__ int   g_part[128];
__device__ float g_h0[(size_t)NMAX * DIN];
__device__ float g_h1[(size_t)NMAX * DIN];
// weight images in mma-fragment order, tf32-rounded: [Wself|Wneigh] (K=256 x DOUT)
__device__ float g_wt0[256 * 128];
__device__ float g_wt1[256 * 128];
__device__ float g_wt2[256 * 64];

__device__ __forceinline__ uint32_t f2tf32(float v) {
    uint32_t r;
    asm("cvt.rna.tf32.f32 %0, %1;" : "=r"(r) : "f"(v));
    return r;
}
__device__ __forceinline__ void mma8(float* c, const uint32_t* a, const uint32_t* b) {
    asm volatile(
        "mma.sync.aligned.m16n8k8.row.col.f32.tf32.tf32.f32 "
        "{%0,%1,%2,%3}, {%4,%5,%6,%7}, {%8,%9}, {%0,%1,%2,%3};"
        : "+f"(c[0]), "+f"(c[1]), "+f"(c[2]), "+f"(c[3])
        : "r"(a[0]), "r"(a[1]), "r"(a[2]), "r"(a[3]), "r"(b[0]), "r"(b[1]));
}

// ---------------- CSR build ----------------
__global__ void k_zero_deg(int n) {
    int i = blockIdx.x * blockDim.x + threadIdx.x;
    if (i < n) g_deg[i] = 0;
}
__global__ void k_count(const int* __restrict__ dst, int e) {
    int i = blockIdx.x * blockDim.x + threadIdx.x;
    if (i < e) atomicAdd(&g_deg[dst[i]], 1);
}
__global__ void k_scan_block(int n) {
    __shared__ int s[1024];
    int tid = threadIdx.x;
    int i = blockIdx.x * 1024 + tid;
    int v = (i < n) ? g_deg[i] : 0;
    s[tid] = v;
    __syncthreads();
    for (int off = 1; off < 1024; off <<= 1) {
        int t = (tid >= off) ? s[tid - off] : 0;
        __syncthreads();
        s[tid] += t;
        __syncthreads();
    }
    if (i < n) g_rowptr[i] = s[tid] - v;
    if (tid == 1023) g_part[blockIdx.x] = s[1023];
}
__global__ void k_scan_part(int nb) {
    __shared__ int s[128];
    int t = threadIdx.x;
    int v = (t < nb) ? g_part[t] : 0;
    s[t] = v;
    __syncthreads();
    for (int off = 1; off < 128; off <<= 1) {
        int u = (t >= off) ? s[t - off] : 0;
        __syncthreads();
        s[t] += u;
        __syncthreads();
    }
    if (t < nb) g_part[t] = s[t] - v;   // exclusive
}
__global__ void k_apply(int n, int e) {
    int i = blockIdx.x * blockDim.x + threadIdx.x;
    if (i < n) {
        int v = g_rowptr[i] + g_part[i >> 10];
        g_rowptr[i] = v;
        g_cursor[i] = v;
    }
    if (i == 0) g_rowptr[n] = e;
}
__global__ void k_fill(const int* __restrict__ src, const int* __restrict__ dst, int e) {
    int i = blockIdx.x * blockDim.x + threadIdx.x;
    if (i < e) {
        int p = atomicAdd(&g_cursor[dst[i]], 1);
        g_adj[p] = src[i];
    }
}
__global__ void k_deginv(int n) {
    int i = blockIdx.x * blockDim.x + threadIdx.x;
    if (i < n) g_deginv[i] = 1.0f / fmaxf((float)g_deg[i], 1.0f);
}

// ---------------- W preprocessing: fragment-order, tf32-rounded B image ----------------
__global__ void k_prepw(const float* __restrict__ Wa, const float* __restrict__ Wb,
                        float* __restrict__ o, int dout) {
    int i = blockIdx.x * blockDim.x + threadIdx.x;
    if (i >= 256 * dout) return;
    int k = i / dout, nn = i % dout;
    float v = (k < 128) ? Wa[k * dout + nn] : Wb[(k - 128) * dout + nn];
    int ksg = k >> 3, nt = nn >> 3;
    int lane = ((nn & 7) << 2) | (k & 3);
    int reg = (k >> 2) & 1;
    o[((ksg * (dout >> 3) + nt) * 32 + lane) * 2 + reg] = __uint_as_float(f2tf32(v));
}

// ---------------- fused agg + GEMM, persistent producer/consumer ----------------
// out[64rows x DOUT] per tile = relu?([h_self | agg][64x256] @ W[256xDOUT] + b)
// warps 0-3 producers (fill smem chunks), warps 4-7 consumers (tf32 mma.sync)
template <int DOUT, bool RELU>
__global__ __launch_bounds__(256)
void k_fused(const float* __restrict__ hin, const float* __restrict__ Wt,
             const float* __restrict__ bias, float* __restrict__ out,
             int n, int ntiles) {
    constexpr int WFLOATS = 256 * DOUT;
    constexpr int PAD = 132;                 // chunk row stride in floats
    constexpr int NTW = DOUT / 32;           // 8-wide n-tiles per consumer warp
    extern __shared__ float sm[];
    float* Wsm = sm;
    float* chunk0 = sm + WFLOATS;
    float* chunk1 = sm + WFLOATS + 64 * PAD;

    int tid = threadIdx.x, wid = tid >> 5, lane = tid & 31;

    // cooperative W image load (already fragment-ordered + tf32)
    {
        const float4* g = (const float4*)Wt;
        float4* s = (float4*)Wsm;
        for (int i = tid; i < WFLOATS / 4; i += 256) s[i] = g[i];
    }
    __syncthreads();

    const float4* h4 = (const float4*)hin;

    if (wid < 4) {
        // ================= producers =================
        int p = wid;
        for (int t = blockIdx.x; t < ntiles; t += gridDim.x) {
            int row0 = t * 64;
            // chunk0: self rows (K 0..127), rows p*16..p*16+15
            for (int i = 0; i < 16; i += 4) {
                float4 v[4];
#pragma unroll
                for (int u = 0; u < 4; ++u) {
                    int r = row0 + p * 16 + i + u;
                    float4 z = {0.f, 0.f, 0.f, 0.f};
                    v[u] = (r < n) ? h4[(size_t)r * 32 + lane] : z;
                }
#pragma unroll
                for (int u = 0; u < 4; ++u) {
                    float* d = chunk0 + (p * 16 + i + u) * PAD + lane * 4;
                    d[0] = __uint_as_float(f2tf32(v[u].x));
                    d[1] = __uint_as_float(f2tf32(v[u].y));
                    d[2] = __uint_as_float(f2tf32(v[u].z));
                    d[3] = __uint_as_float(f2tf32(v[u].w));
                }
            }
            __syncthreads();   // B1: chunk0 ready (consumers mma0 / producers gather)
            // chunk1: aggregated neighbor rows (K 128..255)
            for (int i = 0; i < 16; ++i) {
                int r = row0 + p * 16 + i;
                float ax = 0.f, ay = 0.f, az = 0.f, aw = 0.f;
                if (r < n) {
                    int s = g_rowptr[r];
                    int e = g_rowptr[r + 1];
                    for (int j = s; j < e; j += 8) {
                        int cnt = e - j;
                        if (cnt > 8) cnt = 8;
                        int vi = (lane < cnt) ? g_adj[j + lane] : 0;
                        float4 tt[8];
#pragma unroll
                        for (int u = 0; u < 8; ++u) {
                            int v = __shfl_sync(0xffffffffu, vi, u);
                            float4 z = {0.f, 0.f, 0.f, 0.f};
                            tt[u] = (u < cnt) ? h4[(size_t)v * 32 + lane] : z;
                        }
#pragma unroll
                        for (int u = 0; u < 8; ++u) {
                            ax += tt[u].x; ay += tt[u].y;
                            az += tt[u].z; aw += tt[u].w;
                        }
                    }
                    float di = g_deginv[r];
                    ax *= di; ay *= di; az *= di; aw *= di;
                }
                float* d = chunk1 + (p * 16 + i) * PAD + lane * 4;
                d[0] = __uint_as_float(f2tf32(ax));
                d[1] = __uint_as_float(f2tf32(ay));
                d[2] = __uint_as_float(f2tf32(az));
                d[3] = __uint_as_float(f2tf32(aw));
            }
            __syncthreads();   // B2: chunk1 ready (consumers mma1+epi / producers next self)
        }
    } else {
        // ================= consumers =================
        int wc = wid - 4;
        float bv[NTW][2];
#pragma unroll
        for (int nt = 0; nt < NTW; ++nt) {
            int c = wc * (NTW * 8) + nt * 8 + (lane & 3) * 2;
            bv[nt][0] = bias[c];
            bv[nt][1] = bias[c + 1];
        }
        for (int t = blockIdx.x; t < ntiles; t += gridDim.x) {
            int row0 = t * 64;
            float acc[4][NTW][4];
#pragma unroll
            for (int mt = 0; mt < 4; ++mt)
#pragma unroll
                for (int nt = 0; nt < NTW; ++nt)
#pragma unroll
                    for (int q = 0; q < 4; ++q) acc[mt][nt][q] = 0.f;

            auto mma_chunk = [&](const float* cb, int c) {
#pragma unroll
                for (int ks = 0; ks < 16; ++ks) {
                    uint32_t af[4][4];
#pragma unroll
                    for (int mt = 0; mt < 4; ++mt) {
                        const float* base = cb + (mt * 16 + (lane >> 2)) * PAD + ks * 8 + (lane & 3);
                        af[mt][0] = __float_as_uint(base[0]);
                        af[mt][1] = __float_as_uint(base[8 * PAD]);
                        af[mt][2] = __float_as_uint(base[4]);
                        af[mt][3] = __float_as_uint(base[8 * PAD + 4]);
                    }
                    int ksg = c * 16 + ks;
#pragma unroll
                    for (int nt = 0; nt < NTW; ++nt) {
                        int ntg = wc * NTW + nt;
                        float2 w2 = *(const float2*)(Wsm + ((ksg * (DOUT / 8) + ntg) * 32 + lane) * 2);
                        uint32_t bf[2] = {__float_as_uint(w2.x), __float_as_uint(w2.y)};
#pragma unroll
                        for (int mt = 0; mt < 4; ++mt) mma8(acc[mt][nt], af[mt], bf);
                    }
                }
            };

            __syncthreads();   // B1: chunk0 ready
            mma_chunk(chunk0, 0);
            __syncthreads();   // B2: chunk1 ready
            mma_chunk(chunk1, 1);

            // epilogue
#pragma unroll
            for (int mt = 0; mt < 4; ++mt) {
                int r = row0 + mt * 16 + (lane >> 2);
#pragma unroll
                for (int nt = 0; nt < NTW; ++nt) {
                    int cc = wc * (NTW * 8) + nt * 8 + (lane & 3) * 2;
                    float2 o0, o1;
                    o0.x = acc[mt][nt][0] + bv[nt][0];
                    o0.y = acc[mt][nt][1] + bv[nt][1];
                    o1.x = acc[mt][nt][2] + bv[nt][0];
                    o1.y = acc[mt][nt][3] + bv[nt][1];
                    if (RELU) {
                        o0.x = fmaxf(o0.x, 0.f); o0.y = fmaxf(o0.y, 0.f);
                        o1.x = fmaxf(o1.x, 0.f); o1.y = fmaxf(o1.y, 0.f);
                    }
                    if (r < n)     *(float2*)(out + (size_t)r * DOUT + cc) = o0;
                    if (r + 8 < n) *(float2*)(out + (size_t)(r + 8) * DOUT + cc) = o1;
                }
            }
        }
    }
}

// ---------------- launch ----------------
extern "C" void kernel_launch(void* const* d_in, const int* in_sizes, int n_in,
                              void* d_out, int out_size) {
    const float* x   = (const float*)d_in[0];
    const int*   src = (const int*)d_in[1];
    const int*   dst = (const int*)d_in[2];
    const float* Ws0 = (const float*)d_in[3];
    const float* Wn0 = (const float*)d_in[4];
    const float* b0  = (const float*)d_in[5];
    const float* Ws1 = (const float*)d_in[6];
    const float* Wn1 = (const float*)d_in[7];
    const float* b1  = (const float*)d_in[8];
    const float* Ws2 = (const float*)d_in[9];
    const float* Wn2 = (const float*)d_in[10];
    const float* b2  = (const float*)d_in[11];
    float* out = (float*)d_out;

    int n = in_sizes[0] / 128;
    int e = in_sizes[1];

    float *h0, *h1, *wt0, *wt1, *wt2;
    cudaGetSymbolAddress((void**)&h0,  g_h0);
    cudaGetSymbolAddress((void**)&h1,  g_h1);
    cudaGetSymbolAddress((void**)&wt0, g_wt0);
    cudaGetSymbolAddress((void**)&wt1, g_wt1);
    cudaGetSymbolAddress((void**)&wt2, g_wt2);

    const int SMF128 = (256 * 128 + 2 * 64 * 132) * 4;   // 198656
    const int SMF64  = (256 * 64  + 2 * 64 * 132) * 4;   // 133120
    cudaFuncSetAttribute(k_fused<128, true>,
                         cudaFuncAttributeMaxDynamicSharedMemorySize, SMF128);
    cudaFuncSetAttribute(k_fused<64, false>,
                         cudaFuncAttributeMaxDynamicSharedMemorySize, SMF64);

    int nsm = 148;
    cudaDeviceGetAttribute(&nsm, cudaDevAttrMultiProcessorCount, 0);

    // W preprocessing (fragment order + tf32 round)
    k_prepw<<<(256 * 128 + 255) / 256, 256>>>(Ws0, Wn0, wt0, 128);
    k_prepw<<<(256 * 128 + 255) / 256, 256>>>(Ws1, Wn1, wt1, 128);
    k_prepw<<<(256 * 64 + 255) / 256, 256>>>(Ws2, Wn2, wt2, 64);

    // CSR build
    int nb = (n + 1023) / 1024;
    k_zero_deg<<<(n + 255) / 256, 256>>>(n);
    k_count<<<(e + 255) / 256, 256>>>(dst, e);
    k_scan_block<<<nb, 1024>>>(n);
    k_scan_part<<<1, 128>>>(nb);
    k_apply<<<(n + 255) / 256, 256>>>(n, e);
    k_fill<<<(e + 255) / 256, 256>>>(src, dst, e);
    k_deginv<<<(n + 255) / 256, 256>>>(n);

    int ntiles = (n + 63) / 64;

    k_fused<128, true><<<nsm, 256, SMF128>>>(x,  wt0, b0, h0,  n, ntiles);
    k_fused<128, true><<<nsm, 256, SMF128>>>(h0, wt1, b1, h1,  n, ntiles);
    k_fused<64, false><<<nsm, 256, SMF64 >>>(h1, wt2, b2, out, n, ntiles);
}

// round 5
// speedup vs baseline: 3.6573x; 3.6573x over previous
#include <cuda_runtime.h>
#include <cuda_fp16.h>
#include <cstdint>

#define NMAX 100000
#define EMAX 1600000
#define DIN 128

// ---------------- device scratch ----------------
__device__ int    g_deg[NMAX];
__device__ int    g_rowptr[NMAX + 1];
__device__ int    g_cursor[NMAX];
__device__ int    g_adj[EMAX];
__device__ float  g_deginv[NMAX];
__device__ int    g_part[128];
__device__ __half g_hx[(size_t)NMAX * DIN];   // fp16 copy of x
__device__ __half g_h0[(size_t)NMAX * DIN];
__device__ __half g_h1[(size_t)NMAX * DIN];
__device__ __half g_agg[(size_t)NMAX * DIN];
// weight images in mma-fragment order, tf32-rounded: [Wself|Wneigh] (K=256 x DOUT)
__device__ float  g_wt0[256 * 128];
__device__ float  g_wt1[256 * 128];
__device__ float  g_wt2[256 * 64];

__device__ __forceinline__ uint32_t f2tf32(float v) {
    uint32_t r;
    asm("cvt.rna.tf32.f32 %0, %1;" : "=r"(r) : "f"(v));
    return r;
}
__device__ __forceinline__ void mma8(float* c, const uint32_t* a, const uint32_t* b) {
    asm volatile(
        "mma.sync.aligned.m16n8k8.row.col.f32.tf32.tf32.f32 "
        "{%0,%1,%2,%3}, {%4,%5,%6,%7}, {%8,%9}, {%0,%1,%2,%3};"
        : "+f"(c[0]), "+f"(c[1]), "+f"(c[2]), "+f"(c[3])
        : "r"(a[0]), "r"(a[1]), "r"(a[2]), "r"(a[3]), "r"(b[0]), "r"(b[1]));
}

// ---------------- CSR build ----------------
__global__ void k_zero_deg(int n) {
    int i = blockIdx.x * blockDim.x + threadIdx.x;
    if (i < n) g_deg[i] = 0;
}
__global__ void k_count(const int* __restrict__ dst, int e) {
    int i = blockIdx.x * blockDim.x + threadIdx.x;
    if (i < e) atomicAdd(&g_deg[dst[i]], 1);
}
__global__ void k_scan_block(int n) {
    __shared__ int s[1024];
    int tid = threadIdx.x;
    int i = blockIdx.x * 1024 + tid;
    int v = (i < n) ? g_deg[i] : 0;
    s[tid] = v;
    __syncthreads();
    for (int off = 1; off < 1024; off <<= 1) {
        int t = (tid >= off) ? s[tid - off] : 0;
        __syncthreads();
        s[tid] += t;
        __syncthreads();
    }
    if (i < n) g_rowptr[i] = s[tid] - v;
    if (tid == 1023) g_part[blockIdx.x] = s[1023];
}
__global__ void k_scan_part(int nb) {
    __shared__ int s[128];
    int t = threadIdx.x;
    int v = (t < nb) ? g_part[t] : 0;
    s[t] = v;
    __syncthreads();
    for (int off = 1; off < 128; off <<= 1) {
        int u = (t >= off) ? s[t - off] : 0;
        __syncthreads();
        s[t] += u;
        __syncthreads();
    }
    if (t < nb) g_part[t] = s[t] - v;   // exclusive
}
__global__ void k_apply(int n, int e) {
    int i = blockIdx.x * blockDim.x + threadIdx.x;
    if (i < n) {
        int v = g_rowptr[i] + g_part[i >> 10];
        g_rowptr[i] = v;
        g_cursor[i] = v;
    }
    if (i == 0) g_rowptr[n] = e;
}
__global__ void k_fill(const int* __restrict__ src, const int* __restrict__ dst, int e) {
    int i = blockIdx.x * blockDim.x + threadIdx.x;
    if (i < e) {
        int p = atomicAdd(&g_cursor[dst[i]], 1);
        g_adj[p] = src[i];
    }
}
__global__ void k_deginv(int n) {
    int i = blockIdx.x * blockDim.x + threadIdx.x;
    if (i < n) g_deginv[i] = 1.0f / fmaxf((float)g_deg[i], 1.0f);
}

// ---------------- x -> fp16 ----------------
__global__ void k_x2h(const float* __restrict__ x, __half* __restrict__ hx, int total4) {
    int i = blockIdx.x * blockDim.x + threadIdx.x;
    if (i >= total4) return;
    float4 v = ((const float4*)x)[i];
    __half2 lo = __floats2half2_rn(v.x, v.y);
    __half2 hi = __floats2half2_rn(v.z, v.w);
    uint2 o;
    o.x = *(uint32_t*)&lo;
    o.y = *(uint32_t*)&hi;
    ((uint2*)hx)[i] = o;
}

// ---------------- aggregation: warp per node, fp16 rows ----------------
__global__ void k_agg_h(const __half* __restrict__ hin, __half* __restrict__ agg, int n) {
    int nid = blockIdx.x * 8 + (threadIdx.x >> 5);
    if (nid >= n) return;
    int lane = threadIdx.x & 31;
    int s = g_rowptr[nid];
    int e = g_rowptr[nid + 1];
    const uint2* h2 = (const uint2*)hin;
    float a0 = 0.f, a1 = 0.f, a2 = 0.f, a3 = 0.f;
    int j = s;
    for (; j + 3 < e; j += 4) {
        uint2 t[4];
#pragma unroll
        for (int u = 0; u < 4; ++u)
            t[u] = h2[(size_t)g_adj[j + u] * 32 + lane];
#pragma unroll
        for (int u = 0; u < 4; ++u) {
            float2 fl = __half22float2(*(const __half2*)&t[u].x);
            float2 fh = __half22float2(*(const __half2*)&t[u].y);
            a0 += fl.x; a1 += fl.y; a2 += fh.x; a3 += fh.y;
        }
    }
    for (; j < e; ++j) {
        uint2 t = h2[(size_t)g_adj[j] * 32 + lane];
        float2 fl = __half22float2(*(const __half2*)&t.x);
        float2 fh = __half22float2(*(const __half2*)&t.y);
        a0 += fl.x; a1 += fl.y; a2 += fh.x; a3 += fh.y;
    }
    float di = g_deginv[nid];
    __half2 lo = __floats2half2_rn(a0 * di, a1 * di);
    __half2 hi = __floats2half2_rn(a2 * di, a3 * di);
    uint2 o;
    o.x = *(uint32_t*)&lo;
    o.y = *(uint32_t*)&hi;
    ((uint2*)agg)[(size_t)nid * 32 + lane] = o;
}

// ---------------- W preprocessing: fragment-order, tf32-rounded B image ----------------
__global__ void k_prepw(const float* __restrict__ Wa, const float* __restrict__ Wb,
                        float* __restrict__ o, int dout) {
    int i = blockIdx.x * blockDim.x + threadIdx.x;
    if (i >= 256 * dout) return;
    int k = i / dout, nn = i % dout;
    float v = (k < 128) ? Wa[k * dout + nn] : Wb[(k - 128) * dout + nn];
    int ksg = k >> 3, nt = nn >> 3;
    int lane = ((nn & 7) << 2) | (k & 3);
    int reg = (k >> 2) & 1;
    o[((ksg * (dout >> 3) + nt) * 32 + lane) * 2 + reg] = __uint_as_float(f2tf32(v));
}

// ---------------- tf32 mma.sync GEMM, fp16 A operands ----------------
// C[128 x DOUT] = [h|agg][128 x 256] @ W[256 x DOUT] + b (relu optional)
template <int DOUT, bool RELU, typename OutT>
__global__ __launch_bounds__(256)
void k_mma(const __half* __restrict__ A0, const __half* __restrict__ A1,
           const float* __restrict__ Wt, const float* __restrict__ bias,
           OutT* __restrict__ out, int n) {
    constexpr int NT = DOUT / 16;            // n-tiles per warp
    constexpr int WFLOATS = 256 * DOUT;
    constexpr int STG_FLOATS = 8192;         // one A stage: 128 rows x 64 k
    extern __shared__ float sm[];
    float* Wsm = sm;
    float* Asm = sm + WFLOATS;
    int tid = threadIdx.x, wid = tid >> 5, lane = tid & 31;
    int row0 = blockIdx.x * 128;

    // W image copy (already fragment-ordered + tf32)
    {
        const float4* g = (const float4*)Wt;
        float4* s = (float4*)Wsm;
        for (int i = tid; i < WFLOATS / 4; i += 256) s[i] = g[i];
    }

    // chunk LDG: 128 rows x 64 halves (quarter q of [A0|A1])
    auto ldg_chunk = [&](int q, uint2* v) {
        const uint2* s2 = (const uint2*)((q < 2) ? A0 : A1);
        int cb = (q & 1) * 16;
#pragma unroll
        for (int u = 0; u < 8; ++u) {
            int i = tid + u * 256;
            int r = i >> 4, c4 = i & 15;
            int grow = row0 + r;
            uint2 t = {0u, 0u};
            if (grow < n) t = s2[(size_t)grow * 32 + cb + c4];
            v[u] = t;
        }
    };
    // STS in A-fragment order (fp16 -> fp32 is exact & tf32-representable)
    auto sts_chunk = [&](float* stage, const uint2* v) {
#pragma unroll
        for (int u = 0; u < 8; ++u) {
            int i = tid + u * 256;
            int r = i >> 4, c4 = i & 15;
            int ks = c4 >> 1, mt = r >> 4;
            int lanebase = (r & 7) << 2;
            int reg = ((r >> 3) & 1) | ((c4 & 1) << 1);
            float* base = stage + ((ks * 8 + mt) * 32 + lanebase) * 4 + reg;
            float2 fl = __half22float2(*(const __half2*)&v[u].x);
            float2 fh = __half22float2(*(const __half2*)&v[u].y);
            base[0]  = fl.x;
            base[4]  = fl.y;
            base[8]  = fh.x;
            base[12] = fh.y;
        }
    };

    float acc[2][NT][4];
#pragma unroll
    for (int i = 0; i < 2; ++i)
#pragma unroll
        for (int j = 0; j < NT; ++j)
#pragma unroll
            for (int t = 0; t < 4; ++t) acc[i][j][t] = 0.f;

    int wm = wid >> 1, wn = wid & 1;

    uint2 v[8];
    ldg_chunk(0, v);
    sts_chunk(Asm, v);
    __syncthreads();

#pragma unroll
    for (int q = 0; q < 4; ++q) {
        uint2 nv[8];
        if (q < 3) ldg_chunk(q + 1, nv);

        const float* stage = Asm + (q & 1) * STG_FLOATS;
#pragma unroll
        for (int ks = 0; ks < 8; ++ks) {
            int ksg = q * 8 + ks;
            uint32_t afr[2][4];
#pragma unroll
            for (int i = 0; i < 2; ++i) {
                int mt = wm * 2 + i;
                float4 t = *(const float4*)(stage + ((ks * 8 + mt) * 32 + lane) * 4);
                afr[i][0] = __float_as_uint(t.x);
                afr[i][1] = __float_as_uint(t.y);
                afr[i][2] = __float_as_uint(t.z);
                afr[i][3] = __float_as_uint(t.w);
            }
#pragma unroll
            for (int j = 0; j < NT; ++j) {
                int ntg = wn * NT + j;
                float2 t = *(const float2*)(Wsm + ((ksg * (DOUT / 8) + ntg) * 32 + lane) * 2);
                uint32_t bfr[2] = {__float_as_uint(t.x), __float_as_uint(t.y)};
                mma8(acc[0][j], afr[0], bfr);
                mma8(acc[1][j], afr[1], bfr);
            }
        }

        if (q < 3) {
            __syncthreads();
            sts_chunk(Asm + ((q + 1) & 1) * STG_FLOATS, nv);
            __syncthreads();
        }
    }

    // epilogue
#pragma unroll
    for (int i = 0; i < 2; ++i) {
        int r0g = row0 + wm * 32 + i * 16 + (lane >> 2);
#pragma unroll
        for (int j = 0; j < NT; ++j) {
            int cb = wn * (NT * 8) + j * 8 + (lane & 3) * 2;
            float b0 = bias[cb], b1 = bias[cb + 1];
            float o0x = acc[i][j][0] + b0, o0y = acc[i][j][1] + b1;
            float o1x = acc[i][j][2] + b0, o1y = acc[i][j][3] + b1;
            if (RELU) {
                o0x = fmaxf(o0x, 0.f); o0y = fmaxf(o0y, 0.f);
                o1x = fmaxf(o1x, 0.f); o1y = fmaxf(o1y, 0.f);
            }
            if constexpr (sizeof(OutT) == 2) {
                __half2 p0 = __floats2half2_rn(o0x, o0y);
                __half2 p1 = __floats2half2_rn(o1x, o1y);
                if (r0g < n)
                    *(__half2*)((__half*)out + (size_t)r0g * DOUT + cb) = p0;
                if (r0g + 8 < n)
                    *(__half2*)((__half*)out + (size_t)(r0g + 8) * DOUT + cb) = p1;
            } else {
                float2 p0 = {o0x, o0y}, p1 = {o1x, o1y};
                if (r0g < n)
                    *(float2*)((float*)out + (size_t)r0g * DOUT + cb) = p0;
                if (r0g + 8 < n)
                    *(float2*)((float*)out + (size_t)(r0g + 8) * DOUT + cb) = p1;
            }
        }
    }
}

// ---------------- launch ----------------
extern "C" void kernel_launch(void* const* d_in, const int* in_sizes, int n_in,
                              void* d_out, int out_size) {
    const float* x   = (const float*)d_in[0];
    const int*   src = (const int*)d_in[1];
    const int*   dst = (const int*)d_in[2];
    const float* Ws0 = (const float*)d_in[3];
    const float* Wn0 = (const float*)d_in[4];
    const float* b0  = (const float*)d_in[5];
    const float* Ws1 = (const float*)d_in[6];
    const float* Wn1 = (const float*)d_in[7];
    const float* b1  = (const float*)d_in[8];
    const float* Ws2 = (const float*)d_in[9];
    const float* Wn2 = (const float*)d_in[10];
    const float* b2  = (const float*)d_in[11];
    float* out = (float*)d_out;

    int n = in_sizes[0] / 128;
    int e = in_sizes[1];

    __half *hx, *h0, *h1, *agg;
    float *wt0, *wt1, *wt2;
    cudaGetSymbolAddress((void**)&hx,  g_hx);
    cudaGetSymbolAddress((void**)&h0,  g_h0);
    cudaGetSymbolAddress((void**)&h1,  g_h1);
    cudaGetSymbolAddress((void**)&agg, g_agg);
    cudaGetSymbolAddress((void**)&wt0, g_wt0);
    cudaGetSymbolAddress((void**)&wt1, g_wt1);
    cudaGetSymbolAddress((void**)&wt2, g_wt2);

    const int SM128 = (256 * 128 + 2 * 8192) * 4;   // 196608
    const int SM64  = (256 * 64  + 2 * 8192) * 4;   // 131072
    cudaFuncSetAttribute(k_mma<128, true, __half>,
                         cudaFuncAttributeMaxDynamicSharedMemorySize, SM128);
    cudaFuncSetAttribute(k_mma<64, false, float>,
                         cudaFuncAttributeMaxDynamicSharedMemorySize, SM64);

    // x -> fp16 copy + W preprocessing
    int total4 = n * 32;
    k_x2h<<<(total4 + 255) / 256, 256>>>(x, hx, total4);
    k_prepw<<<(256 * 128 + 255) / 256, 256>>>(Ws0, Wn0, wt0, 128);
    k_prepw<<<(256 * 128 + 255) / 256, 256>>>(Ws1, Wn1, wt1, 128);
    k_prepw<<<(256 * 64 + 255) / 256, 256>>>(Ws2, Wn2, wt2, 64);

    // CSR build
    int nb = (n + 1023) / 1024;
    k_zero_deg<<<(n + 255) / 256, 256>>>(n);
    k_count<<<(e + 255) / 256, 256>>>(dst, e);
    k_scan_block<<<nb, 1024>>>(n);
    k_scan_part<<<1, 128>>>(nb);
    k_apply<<<(n + 255) / 256, 256>>>(n, e);
    k_fill<<<(e + 255) / 256, 256>>>(src, dst, e);
    k_deginv<<<(n + 255) / 256, 256>>>(n);

    int ga = (n + 7) / 8;
    int gm = (n + 127) / 128;

    k_agg_h<<<ga, 256>>>(hx, agg, n);
    k_mma<128, true, __half><<<gm, 256, SM128>>>(hx, agg, wt0, b0, h0, n);
    k_agg_h<<<ga, 256>>>(h0, agg, n);
    k_mma<128, true, __half><<<gm, 256, SM128>>>(h0, agg, wt1, b1, h1, n);
    k_agg_h<<<ga, 256>>>(h1, agg, n);
    k_mma<64, false, float><<<gm, 256, SM64>>>(h1, agg, wt2, b2, out, n);
}

// round 6
// speedup vs baseline: 4.3690x; 1.1946x over previous
#include <cuda_runtime.h>
#include <cuda_fp16.h>
#include <cstdint>

#define NMAX 100000
#define EMAX 1600000

// ---------------- device scratch ----------------
__device__ int    g_deg[NMAX];
__device__ int    g_rowptr[NMAX + 1];
__device__ int    g_cursor[NMAX];
__device__ int    g_adj[EMAX];
__device__ float  g_deginv[NMAX];
__device__ int    g_part[128];
__device__ __half g_hx[(size_t)NMAX * 128];   // fp16 x / layer activations
__device__ __half g_hA[(size_t)NMAX * 128];
__device__ __half g_ys[(size_t)NMAX * 128];   // self-path GEMM result (+bias)
__device__ __half g_z[(size_t)NMAX * 128];    // neighbor-path GEMM result
// weight images in m16n8k16 fragment order, fp16: [Ws|Wn] (K=128 x 2*DOUT)
__device__ __half g_wt0[128 * 256];
__device__ __half g_wt1[128 * 256];
__device__ __half g_wt2[128 * 128];

__device__ __forceinline__ uint32_t smem_u32(const void* p) {
    uint32_t a;
    asm("{ .reg .u64 t; cvta.to.shared.u64 t, %1; cvt.u32.u64 %0, t; }" : "=r"(a) : "l"(p));
    return a;
}
__device__ __forceinline__ void ldmatrix_x4(uint32_t* r, uint32_t addr) {
    asm volatile("ldmatrix.sync.aligned.m8n8.x4.shared.b16 {%0,%1,%2,%3}, [%4];"
                 : "=r"(r[0]), "=r"(r[1]), "=r"(r[2]), "=r"(r[3]) : "r"(addr));
}
__device__ __forceinline__ void mma16(float* c, const uint32_t* a, const uint32_t* b) {
    asm volatile(
        "mma.sync.aligned.m16n8k16.row.col.f32.f16.f16.f32 "
        "{%0,%1,%2,%3},{%4,%5,%6,%7},{%8,%9},{%0,%1,%2,%3};"
        : "+f"(c[0]), "+f"(c[1]), "+f"(c[2]), "+f"(c[3])
        : "r"(a[0]), "r"(a[1]), "r"(a[2]), "r"(a[3]), "r"(b[0]), "r"(b[1]));
}

// ---------------- CSR build ----------------
__global__ void k_zero_deg(int n) {
    int i = blockIdx.x * blockDim.x + threadIdx.x;
    if (i < n) g_deg[i] = 0;
}
__global__ void k_count(const int* __restrict__ dst, int e) {
    int i = blockIdx.x * blockDim.x + threadIdx.x;
    if (i < e) atomicAdd(&g_deg[dst[i]], 1);
}
__global__ void k_scan_block(int n) {
    __shared__ int s[1024];
    int tid = threadIdx.x;
    int i = blockIdx.x * 1024 + tid;
    int v = (i < n) ? g_deg[i] : 0;
    s[tid] = v;
    __syncthreads();
    for (int off = 1; off < 1024; off <<= 1) {
        int t = (tid >= off) ? s[tid - off] : 0;
        __syncthreads();
        s[tid] += t;
        __syncthreads();
    }
    if (i < n) g_rowptr[i] = s[tid] - v;
    if (tid == 1023) g_part[blockIdx.x] = s[1023];
}
__global__ void k_scan_part(int nb) {
    __shared__ int s[128];
    int t = threadIdx.x;
    int v = (t < nb) ? g_part[t] : 0;
    s[t] = v;
    __syncthreads();
    for (int off = 1; off < 128; off <<= 1) {
        int u = (t >= off) ? s[t - off] : 0;
        __syncthreads();
        s[t] += u;
        __syncthreads();
    }
    if (t < nb) g_part[t] = s[t] - v;   // exclusive
}
__global__ void k_apply(int n, int e) {
    int i = blockIdx.x * blockDim.x + threadIdx.x;
    if (i < n) {
        int v = g_rowptr[i] + g_part[i >> 10];
        g_rowptr[i] = v;
        g_cursor[i] = v;
    }
    if (i == 0) g_rowptr[n] = e;
}
__global__ void k_fill(const int* __restrict__ src, const int* __restrict__ dst, int e) {
    int i = blockIdx.x * blockDim.x + threadIdx.x;
    if (i < e) {
        int p = atomicAdd(&g_cursor[dst[i]], 1);
        g_adj[p] = src[i];
    }
}
__global__ void k_deginv(int n) {
    int i = blockIdx.x * blockDim.x + threadIdx.x;
    if (i < n) g_deginv[i] = 1.0f / fmaxf((float)g_deg[i], 1.0f);
}

// ---------------- x -> fp16 ----------------
__global__ void k_x2h(const float* __restrict__ x, __half* __restrict__ hx, int total4) {
    int i = blockIdx.x * blockDim.x + threadIdx.x;
    if (i >= total4) return;
    float4 v = ((const float4*)x)[i];
    __half2 lo = __floats2half2_rn(v.x, v.y);
    __half2 hi = __floats2half2_rn(v.z, v.w);
    uint2 o;
    o.x = *(uint32_t*)&lo;
    o.y = *(uint32_t*)&hi;
    ((uint2*)hx)[i] = o;
}

// ---------------- W preprocessing: m16n8k16 B-fragment order, fp16 ----------------
// image covers [Ws | Wn]: K=128 rows, 2*dout cols
__global__ void k_prepw(const float* __restrict__ Ws, const float* __restrict__ Wn,
                        __half* __restrict__ o, int dout) {
    int i = blockIdx.x * blockDim.x + threadIdx.x;
    int dout2 = 2 * dout;
    if (i >= 128 * dout2) return;
    int k = i / dout2, nn = i % dout2;
    float v = (nn < dout) ? Ws[k * dout + nn] : Wn[k * dout + nn - dout];
    int NT2 = dout2 >> 3;
    int ks = k >> 4, nt = nn >> 3;
    int lane = ((nn & 7) << 2) | ((k & 7) >> 1);
    int reg = (k >> 3) & 1;
    int idx = ((((ks * NT2 + nt) * 32 + lane) * 2 + reg) << 1) | (k & 1);
    o[idx] = __float2half(v);
}

// ---------------- fp16 HMMA GEMM: [ys|z] = A[128rows x 128] @ Wimg[128 x 2*DOUT] ----------------
template <int DOUT>
__global__ __launch_bounds__(256, 1)
void k_gemm(const __half* __restrict__ A, const __half* __restrict__ Wimg,
            const float* __restrict__ bias, __half* __restrict__ ys,
            __half* __restrict__ z, int n) {
    constexpr int DOUT2 = 2 * DOUT;
    constexpr int NT2 = DOUT2 / 8;
    constexpr int NT = NT2 / 2;          // n-tiles per warp
    constexpr int ASTRIDE = 136;         // padded halves per A row
    extern __shared__ __half smh[];
    __half* Wsm = smh;                   // 128 * DOUT2 halves, fragment order
    __half* Asm = smh + 128 * DOUT2;     // 128 * 136 halves, row-major padded
    int tid = threadIdx.x, wid = tid >> 5, lane = tid & 31;
    int row0 = blockIdx.x * 128;

    // W image copy
    {
        const uint4* g = (const uint4*)Wimg;
        uint4* s = (uint4*)Wsm;
        for (int i = tid; i < 128 * DOUT2 / 8; i += 256) s[i] = g[i];
    }
    // A fill: 128 rows x 32 uint2
    {
        const uint2* g = (const uint2*)A;
#pragma unroll
        for (int u = 0; u < 16; ++u) {
            int idx = tid + u * 256;
            int r = idx >> 5, c = idx & 31;
            int gr = row0 + r;
            uint2 t = {0u, 0u};
            if (gr < n) t = g[(size_t)gr * 32 + c];
            *(uint2*)(Asm + r * ASTRIDE + c * 4) = t;
        }
    }
    __syncthreads();

    int wm = wid & 3, wn = wid >> 2;
    float acc[2][NT][4];
#pragma unroll
    for (int i = 0; i < 2; ++i)
#pragma unroll
        for (int j = 0; j < NT; ++j)
#pragma unroll
            for (int q = 0; q < 4; ++q) acc[i][j][q] = 0.f;

    uint32_t abase = smem_u32(Asm);
#pragma unroll
    for (int ks = 0; ks < 8; ++ks) {
        uint32_t af[2][4];
#pragma unroll
        for (int i = 0; i < 2; ++i) {
            int row = (wm * 2 + i) * 16 + (lane & 15);
            int col = ks * 16 + (lane >> 4) * 8;
            ldmatrix_x4(af[i], abase + (row * ASTRIDE + col) * 2);
        }
#pragma unroll
        for (int nt = 0; nt < NT; ++nt) {
            int ntg = wn * NT + nt;
            uint2 b2 = *(const uint2*)(Wsm + ((ks * NT2 + ntg) * 32 + lane) * 4);
            uint32_t bf[2] = {b2.x, b2.y};
            mma16(acc[0][nt], af[0], bf);
            mma16(acc[1][nt], af[1], bf);
        }
    }

    // epilogue: wn==0 warps write ys (+bias), wn==1 warps write z
    int gp = lane >> 2, tg = lane & 3;
#pragma unroll
    for (int i = 0; i < 2; ++i) {
        int r = row0 + (wm * 2 + i) * 16 + gp;
#pragma unroll
        for (int nt = 0; nt < NT; ++nt) {
            int cc = (wn * NT + nt) * 8 + tg * 2;
            if (wn == 0) {
                float b0 = bias[cc], b1 = bias[cc + 1];
                __half2 p0 = __floats2half2_rn(acc[i][nt][0] + b0, acc[i][nt][1] + b1);
                __half2 p1 = __floats2half2_rn(acc[i][nt][2] + b0, acc[i][nt][3] + b1);
                if (r < n)     *(__half2*)(ys + (size_t)r * DOUT + cc) = p0;
                if (r + 8 < n) *(__half2*)(ys + (size_t)(r + 8) * DOUT + cc) = p1;
            } else {
                int c2 = cc - DOUT;
                __half2 p0 = __floats2half2_rn(acc[i][nt][0], acc[i][nt][1]);
                __half2 p1 = __floats2half2_rn(acc[i][nt][2], acc[i][nt][3]);
                if (r < n)     *(__half2*)(z + (size_t)r * DOUT + c2) = p0;
                if (r + 8 < n) *(__half2*)(z + (size_t)(r + 8) * DOUT + c2) = p1;
            }
        }
    }
}

// ---------------- combine: out = act(ys + mean_gather(z)) ----------------
template <int DOUT, bool RELU, typename OutT>
__global__ void k_comb(const __half* __restrict__ z, const __half* __restrict__ ys,
                       OutT* __restrict__ out, int n) {
    int nid = blockIdx.x * 8 + (threadIdx.x >> 5);
    if (nid >= n) return;
    int lane = threadIdx.x & 31;
    int s = g_rowptr[nid];
    int e = g_rowptr[nid + 1];
    float di = g_deginv[nid];

    if constexpr (DOUT == 128) {
        const uint2* z2 = (const uint2*)z;
        float a0 = 0.f, a1 = 0.f, a2 = 0.f, a3 = 0.f;
        int j = s;
        for (; j + 3 < e; j += 4) {
            uint2 t[4];
#pragma unroll
            for (int u = 0; u < 4; ++u) t[u] = z2[(size_t)g_adj[j + u] * 32 + lane];
#pragma unroll
            for (int u = 0; u < 4; ++u) {
                float2 fl = __half22float2(*(const __half2*)&t[u].x);
                float2 fh = __half22float2(*(const __half2*)&t[u].y);
                a0 += fl.x; a1 += fl.y; a2 += fh.x; a3 += fh.y;
            }
        }
        for (; j < e; ++j) {
            uint2 t = z2[(size_t)g_adj[j] * 32 + lane];
            float2 fl = __half22float2(*(const __half2*)&t.x);
            float2 fh = __half22float2(*(const __half2*)&t.y);
            a0 += fl.x; a1 += fl.y; a2 += fh.x; a3 += fh.y;
        }
        uint2 yv = ((const uint2*)ys)[(size_t)nid * 32 + lane];
        float2 yl = __half22float2(*(const __half2*)&yv.x);
        float2 yh = __half22float2(*(const __half2*)&yv.y);
        float f0 = a0 * di + yl.x, f1 = a1 * di + yl.y;
        float f2 = a2 * di + yh.x, f3 = a3 * di + yh.y;
        if (RELU) {
            f0 = fmaxf(f0, 0.f); f1 = fmaxf(f1, 0.f);
            f2 = fmaxf(f2, 0.f); f3 = fmaxf(f3, 0.f);
        }
        __half2 lo = __floats2half2_rn(f0, f1);
        __half2 hi = __floats2half2_rn(f2, f3);
        uint2 o;
        o.x = *(uint32_t*)&lo;
        o.y = *(uint32_t*)&hi;
        ((uint2*)out)[(size_t)nid * 32 + lane] = o;
    } else {
        // DOUT == 64, fp32 output, no relu path used here
        const uint32_t* z1 = (const uint32_t*)z;
        float a0 = 0.f, a1 = 0.f;
        int j = s;
        for (; j + 3 < e; j += 4) {
            uint32_t t[4];
#pragma unroll
            for (int u = 0; u < 4; ++u) t[u] = z1[(size_t)g_adj[j + u] * 32 + lane];
#pragma unroll
            for (int u = 0; u < 4; ++u) {
                float2 f = __half22float2(*(const __half2*)&t[u]);
                a0 += f.x; a1 += f.y;
            }
        }
        for (; j < e; ++j) {
            uint32_t t = z1[(size_t)g_adj[j] * 32 + lane];
            float2 f = __half22float2(*(const __half2*)&t);
            a0 += f.x; a1 += f.y;
        }
        uint32_t yv = ((const uint32_t*)ys)[(size_t)nid * 32 + lane];
        float2 yf = __half22float2(*(const __half2*)&yv);
        float2 o;
        o.x = a0 * di + yf.x;
        o.y = a1 * di + yf.y;
        if (RELU) { o.x = fmaxf(o.x, 0.f); o.y = fmaxf(o.y, 0.f); }
        ((float2*)out)[(size_t)nid * 32 + lane] = o;
    }
}

// ---------------- launch ----------------
extern "C" void kernel_launch(void* const* d_in, const int* in_sizes, int n_in,
                              void* d_out, int out_size) {
    const float* x   = (const float*)d_in[0];
    const int*   src = (const int*)d_in[1];
    const int*   dst = (const int*)d_in[2];
    const float* Ws0 = (const float*)d_in[3];
    const float* Wn0 = (const float*)d_in[4];
    const float* b0  = (const float*)d_in[5];
    const float* Ws1 = (const float*)d_in[6];
    const float* Wn1 = (const float*)d_in[7];
    const float* b1  = (const float*)d_in[8];
    const float* Ws2 = (const float*)d_in[9];
    const float* Wn2 = (const float*)d_in[10];
    const float* b2  = (const float*)d_in[11];
    float* out = (float*)d_out;

    int n = in_sizes[0] / 128;
    int e = in_sizes[1];

    __half *hx, *hA, *ys, *z, *wt0, *wt1, *wt2;
    cudaGetSymbolAddress((void**)&hx,  g_hx);
    cudaGetSymbolAddress((void**)&hA,  g_hA);
    cudaGetSymbolAddress((void**)&ys,  g_ys);
    cudaGetSymbolAddress((void**)&z,   g_z);
    cudaGetSymbolAddress((void**)&wt0, g_wt0);
    cudaGetSymbolAddress((void**)&wt1, g_wt1);
    cudaGetSymbolAddress((void**)&wt2, g_wt2);

    const int SM128 = (128 * 256 + 128 * 136) * 2;   // 100352
    const int SM64  = (128 * 128 + 128 * 136) * 2;   // 67584
    cudaFuncSetAttribute(k_gemm<128>,
                         cudaFuncAttributeMaxDynamicSharedMemorySize, SM128);
    cudaFuncSetAttribute(k_gemm<64>,
                         cudaFuncAttributeMaxDynamicSharedMemorySize, SM64);

    // x -> fp16 + W images
    int total4 = n * 32;
    k_x2h<<<(total4 + 255) / 256, 256>>>(x, hx, total4);
    k_prepw<<<(128 * 256 + 255) / 256, 256>>>(Ws0, Wn0, wt0, 128);
    k_prepw<<<(128 * 256 + 255) / 256, 256>>>(Ws1, Wn1, wt1, 128);
    k_prepw<<<(128 * 128 + 255) / 256, 256>>>(Ws2, Wn2, wt2, 64);

    // CSR build
    int nb = (n + 1023) / 1024;
    k_zero_deg<<<(n + 255) / 256, 256>>>(n);
    k_count<<<(e + 255) / 256, 256>>>(dst, e);
    k_scan_block<<<nb, 1024>>>(n);
    k_scan_part<<<1, 128>>>(nb);
    k_apply<<<(n + 255) / 256, 256>>>(n, e);
    k_fill<<<(e + 255) / 256, 256>>>(src, dst, e);
    k_deginv<<<(n + 255) / 256, 256>>>(n);

    int ga = (n + 7) / 8;
    int gm = (n + 127) / 128;

    // layer 0: hx -> hA
    k_gemm<128><<<gm, 256, SM128>>>(hx, wt0, b0, ys, z, n);
    k_comb<128, true, __half><<<ga, 256>>>(z, ys, hA, n);
    // layer 1: hA -> hx (reuse)
    k_gemm<128><<<gm, 256, SM128>>>(hA, wt1, b1, ys, z, n);
    k_comb<128, true, __half><<<ga, 256>>>(z, ys, hx, n);
    // layer 2: hx -> out (fp32, no relu)
    k_gemm<64><<<gm, 256, SM64>>>(hx, wt2, b2, ys, z, n);
    k_comb<64, false, float><<<ga, 256>>>(z, ys, out, n);
}

// round 7
// speedup vs baseline: 4.5882x; 1.0502x over previous
#include <cuda_runtime.h>
#include <cuda_fp16.h>
#include <cstdint>

#define NMAX 100000
#define EMAX 1600000

// ---------------- device scratch ----------------
__device__ int    g_deg[NMAX];
__device__ int    g_rowptr[NMAX + 1];
__device__ int    g_cursor[NMAX];
__device__ int    g_adj[EMAX];
__device__ float  g_deginv[NMAX];
__device__ int    g_part[128];
__device__ __half g_hx[(size_t)NMAX * 128];   // fp16 x / layer activations
__device__ __half g_hA[(size_t)NMAX * 128];
__device__ __half g_ys[(size_t)NMAX * 128];   // self-path GEMM result (+bias)
__device__ __half g_z[(size_t)NMAX * 128];    // neighbor-path GEMM result
// weight images in m16n8k16 fragment order, fp16: [Ws|Wn] (K=128 x 2*DOUT)
__device__ __half g_wt0[128 * 256];
__device__ __half g_wt1[128 * 256];
__device__ __half g_wt2[128 * 128];

__device__ __forceinline__ uint32_t smem_u32(const void* p) {
    uint32_t a;
    asm("{ .reg .u64 t; cvta.to.shared.u64 t, %1; cvt.u32.u64 %0, t; }" : "=r"(a) : "l"(p));
    return a;
}
__device__ __forceinline__ void ldmatrix_x4(uint32_t* r, uint32_t addr) {
    asm volatile("ldmatrix.sync.aligned.m8n8.x4.shared.b16 {%0,%1,%2,%3}, [%4];"
                 : "=r"(r[0]), "=r"(r[1]), "=r"(r[2]), "=r"(r[3]) : "r"(addr));
}
__device__ __forceinline__ void mma16(float* c, const uint32_t* a, const uint32_t* b) {
    asm volatile(
        "mma.sync.aligned.m16n8k16.row.col.f32.f16.f16.f32 "
        "{%0,%1,%2,%3},{%4,%5,%6,%7},{%8,%9},{%0,%1,%2,%3};"
        : "+f"(c[0]), "+f"(c[1]), "+f"(c[2]), "+f"(c[3])
        : "r"(a[0]), "r"(a[1]), "r"(a[2]), "r"(a[3]), "r"(b[0]), "r"(b[1]));
}

// ---------------- CSR build ----------------
__global__ void k_zero_deg(int n) {
    int i = blockIdx.x * blockDim.x + threadIdx.x;
    if (i < n) g_deg[i] = 0;
}
__global__ void k_count(const int* __restrict__ dst, int e) {
    int i = blockIdx.x * blockDim.x + threadIdx.x;
    if (i < e) atomicAdd(&g_deg[dst[i]], 1);
}
__global__ void k_scan_block(int n) {
    __shared__ int s[1024];
    int tid = threadIdx.x;
    int i = blockIdx.x * 1024 + tid;
    int v = (i < n) ? g_deg[i] : 0;
    s[tid] = v;
    __syncthreads();
    for (int off = 1; off < 1024; off <<= 1) {
        int t = (tid >= off) ? s[tid - off] : 0;
        __syncthreads();
        s[tid] += t;
        __syncthreads();
    }
    if (i < n) g_rowptr[i] = s[tid] - v;
    if (tid == 1023) g_part[blockIdx.x] = s[1023];
}
__global__ void k_scan_part(int nb) {
    __shared__ int s[128];
    int t = threadIdx.x;
    int v = (t < nb) ? g_part[t] : 0;
    s[t] = v;
    __syncthreads();
    for (int off = 1; off < 128; off <<= 1) {
        int u = (t >= off) ? s[t - off] : 0;
        __syncthreads();
        s[t] += u;
        __syncthreads();
    }
    if (t < nb) g_part[t] = s[t] - v;   // exclusive
}
__global__ void k_apply(int n, int e) {
    int i = blockIdx.x * blockDim.x + threadIdx.x;
    if (i < n) {
        int v = g_rowptr[i] + g_part[i >> 10];
        g_rowptr[i] = v;
        g_cursor[i] = v;
        g_deginv[i] = 1.0f / fmaxf((float)g_deg[i], 1.0f);   // fused deginv
    }
    if (i == 0) g_rowptr[n] = e;
}
__global__ void k_fill(const int* __restrict__ src, const int* __restrict__ dst, int e) {
    int i = blockIdx.x * blockDim.x + threadIdx.x;
    if (i < e) {
        int p = atomicAdd(&g_cursor[dst[i]], 1);
        g_adj[p] = src[i];
    }
}

// ---------------- x -> fp16 ----------------
__global__ void k_x2h(const float* __restrict__ x, __half* __restrict__ hx, int total4) {
    int i = blockIdx.x * blockDim.x + threadIdx.x;
    if (i >= total4) return;
    float4 v = ((const float4*)x)[i];
    __half2 lo = __floats2half2_rn(v.x, v.y);
    __half2 hi = __floats2half2_rn(v.z, v.w);
    uint2 o;
    o.x = *(uint32_t*)&lo;
    o.y = *(uint32_t*)&hi;
    ((uint2*)hx)[i] = o;
}

// ---------------- W preprocessing: m16n8k16 B-fragment order, fp16 ----------------
__global__ void k_prepw(const float* __restrict__ Ws, const float* __restrict__ Wn,
                        __half* __restrict__ o, int dout) {
    int i = blockIdx.x * blockDim.x + threadIdx.x;
    int dout2 = 2 * dout;
    if (i >= 128 * dout2) return;
    int k = i / dout2, nn = i % dout2;
    float v = (nn < dout) ? Ws[k * dout + nn] : Wn[k * dout + nn - dout];
    int NT2 = dout2 >> 3;
    int ks = k >> 4, nt = nn >> 3;
    int lane = ((nn & 7) << 2) | ((k & 7) >> 1);
    int reg = (k >> 3) & 1;
    int idx = ((((ks * NT2 + nt) * 32 + lane) * 2 + reg) << 1) | (k & 1);
    o[idx] = __float2half(v);
}

// ---------------- fp16 HMMA GEMM: [ys|z] = A[128rows x 128] @ Wimg[128 x 2*DOUT] ----------------
template <int DOUT>
__global__ __launch_bounds__(256, 1)
void k_gemm(const __half* __restrict__ A, const __half* __restrict__ Wimg,
            const float* __restrict__ bias, __half* __restrict__ ys,
            __half* __restrict__ z, int n) {
    constexpr int DOUT2 = 2 * DOUT;
    constexpr int NT2 = DOUT2 / 8;
    constexpr int NT = NT2 / 2;          // n-tiles per warp
    constexpr int ASTRIDE = 136;         // padded halves per A row
    extern __shared__ __half smh[];
    __half* Wsm = smh;                   // 128 * DOUT2 halves, fragment order
    __half* Asm = smh + 128 * DOUT2;     // 128 * 136 halves, row-major padded
    int tid = threadIdx.x, wid = tid >> 5, lane = tid & 31;
    int row0 = blockIdx.x * 128;

    // W image copy
    {
        const uint4* g = (const uint4*)Wimg;
        uint4* s = (uint4*)Wsm;
        for (int i = tid; i < 128 * DOUT2 / 8; i += 256) s[i] = g[i];
    }
    // A fill: 128 rows x 32 uint2
    {
        const uint2* g = (const uint2*)A;
#pragma unroll
        for (int u = 0; u < 16; ++u) {
            int idx = tid + u * 256;
            int r = idx >> 5, c = idx & 31;
            int gr = row0 + r;
            uint2 t = {0u, 0u};
            if (gr < n) t = g[(size_t)gr * 32 + c];
            *(uint2*)(Asm + r * ASTRIDE + c * 4) = t;
        }
    }
    __syncthreads();

    int wm = wid & 3, wn = wid >> 2;
    float acc[2][NT][4];
#pragma unroll
    for (int i = 0; i < 2; ++i)
#pragma unroll
        for (int j = 0; j < NT; ++j)
#pragma unroll
            for (int q = 0; q < 4; ++q) acc[i][j][q] = 0.f;

    uint32_t abase = smem_u32(Asm);
#pragma unroll
    for (int ks = 0; ks < 8; ++ks) {
        uint32_t af[2][4];
#pragma unroll
        for (int i = 0; i < 2; ++i) {
            int row = (wm * 2 + i) * 16 + (lane & 15);
            int col = ks * 16 + (lane >> 4) * 8;
            ldmatrix_x4(af[i], abase + (row * ASTRIDE + col) * 2);
        }
#pragma unroll
        for (int nt = 0; nt < NT; ++nt) {
            int ntg = wn * NT + nt;
            uint2 b2 = *(const uint2*)(Wsm + ((ks * NT2 + ntg) * 32 + lane) * 4);
            uint32_t bf[2] = {b2.x, b2.y};
            mma16(acc[0][nt], af[0], bf);
            mma16(acc[1][nt], af[1], bf);
        }
    }

    // epilogue: wn==0 warps write ys (+bias), wn==1 warps write z
    int gp = lane >> 2, tg = lane & 3;
#pragma unroll
    for (int i = 0; i < 2; ++i) {
        int r = row0 + (wm * 2 + i) * 16 + gp;
#pragma unroll
        for (int nt = 0; nt < NT; ++nt) {
            int cc = (wn * NT + nt) * 8 + tg * 2;
            if (wn == 0) {
                float b0 = bias[cc], b1 = bias[cc + 1];
                __half2 p0 = __floats2half2_rn(acc[i][nt][0] + b0, acc[i][nt][1] + b1);
                __half2 p1 = __floats2half2_rn(acc[i][nt][2] + b0, acc[i][nt][3] + b1);
                if (r < n)     *(__half2*)(ys + (size_t)r * DOUT + cc) = p0;
                if (r + 8 < n) *(__half2*)(ys + (size_t)(r + 8) * DOUT + cc) = p1;
            } else {
                int c2 = cc - DOUT;
                __half2 p0 = __floats2half2_rn(acc[i][nt][0], acc[i][nt][1]);
                __half2 p1 = __floats2half2_rn(acc[i][nt][2], acc[i][nt][3]);
                if (r < n)     *(__half2*)(z + (size_t)r * DOUT + c2) = p0;
                if (r + 8 < n) *(__half2*)(z + (size_t)(r + 8) * DOUT + c2) = p1;
            }
        }
    }
}

// ---------------- combine: out = act(ys + mean_gather(z)) ----------------
template <int DOUT, bool RELU, typename OutT>
__global__ void k_comb(const __half* __restrict__ z, const __half* __restrict__ ys,
                       OutT* __restrict__ out, int n) {
    int nid = blockIdx.x * 8 + (threadIdx.x >> 5);
    if (nid >= n) return;
    int lane = threadIdx.x & 31;
    int s = g_rowptr[nid];
    int e = g_rowptr[nid + 1];
    float di = g_deginv[nid];

    if constexpr (DOUT == 128) {
        const uint2* z2 = (const uint2*)z;
        float a0 = 0.f, a1 = 0.f, a2 = 0.f, a3 = 0.f;
        int j = s;
        for (; j + 7 < e; j += 8) {
            uint2 t[8];
#pragma unroll
            for (int u = 0; u < 8; ++u) t[u] = z2[(size_t)g_adj[j + u] * 32 + lane];
#pragma unroll
            for (int u = 0; u < 8; ++u) {
                float2 fl = __half22float2(*(const __half2*)&t[u].x);
                float2 fh = __half22float2(*(const __half2*)&t[u].y);
                a0 += fl.x; a1 += fl.y; a2 += fh.x; a3 += fh.y;
            }
        }
        for (; j < e; ++j) {
            uint2 t = z2[(size_t)g_adj[j] * 32 + lane];
            float2 fl = __half22float2(*(const __half2*)&t.x);
            float2 fh = __half22float2(*(const __half2*)&t.y);
            a0 += fl.x; a1 += fl.y; a2 += fh.x; a3 += fh.y;
        }
        uint2 yv = ((const uint2*)ys)[(size_t)nid * 32 + lane];
        float2 yl = __half22float2(*(const __half2*)&yv.x);
        float2 yh = __half22float2(*(const __half2*)&yv.y);
        float f0 = a0 * di + yl.x, f1 = a1 * di + yl.y;
        float f2 = a2 * di + yh.x, f3 = a3 * di + yh.y;
        if (RELU) {
            f0 = fmaxf(f0, 0.f); f1 = fmaxf(f1, 0.f);
            f2 = fmaxf(f2, 0.f); f3 = fmaxf(f3, 0.f);
        }
        __half2 lo = __floats2half2_rn(f0, f1);
        __half2 hi = __floats2half2_rn(f2, f3);
        uint2 o;
        o.x = *(uint32_t*)&lo;
        o.y = *(uint32_t*)&hi;
        ((uint2*)out)[(size_t)nid * 32 + lane] = o;
    } else {
        const uint32_t* z1 = (const uint32_t*)z;
        float a0 = 0.f, a1 = 0.f;
        int j = s;
        for (; j + 7 < e; j += 8) {
            uint32_t t[8];
#pragma unroll
            for (int u = 0; u < 8; ++u) t[u] = z1[(size_t)g_adj[j + u] * 32 + lane];
#pragma unroll
            for (int u = 0; u < 8; ++u) {
                float2 f = __half22float2(*(const __half2*)&t[u]);
                a0 += f.x; a1 += f.y;
            }
        }
        for (; j < e; ++j) {
            uint32_t t = z1[(size_t)g_adj[j] * 32 + lane];
            float2 f = __half22float2(*(const __half2*)&t);
            a0 += f.x; a1 += f.y;
        }
        uint32_t yv = ((const uint32_t*)ys)[(size_t)nid * 32 + lane];
        float2 yf = __half22float2(*(const __half2*)&yv);
        float2 o;
        o.x = a0 * di + yf.x;
        o.y = a1 * di + yf.y;
        if (RELU) { o.x = fmaxf(o.x, 0.f); o.y = fmaxf(o.y, 0.f); }
        ((float2*)out)[(size_t)nid * 32 + lane] = o;
    }
}

// ---------------- launch ----------------
extern "C" void kernel_launch(void* const* d_in, const int* in_sizes, int n_in,
                              void* d_out, int out_size) {
    const float* x   = (const float*)d_in[0];
    const int*   src = (const int*)d_in[1];
    const int*   dst = (const int*)d_in[2];
    const float* Ws0 = (const float*)d_in[3];
    const float* Wn0 = (const float*)d_in[4];
    const float* b0  = (const float*)d_in[5];
    const float* Ws1 = (const float*)d_in[6];
    const float* Wn1 = (const float*)d_in[7];
    const float* b1  = (const float*)d_in[8];
    const float* Ws2 = (const float*)d_in[9];
    const float* Wn2 = (const float*)d_in[10];
    const float* b2  = (const float*)d_in[11];
    float* out = (float*)d_out;

    int n = in_sizes[0] / 128;
    int e = in_sizes[1];

    __half *hx, *hA, *ys, *z, *wt0, *wt1, *wt2;
    cudaGetSymbolAddress((void**)&hx,  g_hx);
    cudaGetSymbolAddress((void**)&hA,  g_hA);
    cudaGetSymbolAddress((void**)&ys,  g_ys);
    cudaGetSymbolAddress((void**)&z,   g_z);
    cudaGetSymbolAddress((void**)&wt0, g_wt0);
    cudaGetSymbolAddress((void**)&wt1, g_wt1);
    cudaGetSymbolAddress((void**)&wt2, g_wt2);

    const int SM128 = (128 * 256 + 128 * 136) * 2;   // 100352
    const int SM64  = (128 * 128 + 128 * 136) * 2;   // 67584
    cudaFuncSetAttribute(k_gemm<128>,
                         cudaFuncAttributeMaxDynamicSharedMemorySize, SM128);
    cudaFuncSetAttribute(k_gemm<64>,
                         cudaFuncAttributeMaxDynamicSharedMemorySize, SM64);

    // ---- fork: CSR chain on side stream, activation chain on main ----
    cudaStream_t s2;
    cudaStreamCreateWithFlags(&s2, cudaStreamNonBlocking);
    cudaEvent_t evFork, evJoin;
    cudaEventCreateWithFlags(&evFork, cudaEventDisableTiming);
    cudaEventCreateWithFlags(&evJoin, cudaEventDisableTiming);

    cudaEventRecord(evFork, 0);
    cudaStreamWaitEvent(s2, evFork, 0);

    // CSR branch (stream s2)
    int nb = (n + 1023) / 1024;
    k_zero_deg<<<(n + 255) / 256, 256, 0, s2>>>(n);
    k_count<<<(e + 255) / 256, 256, 0, s2>>>(dst, e);
    k_scan_block<<<nb, 1024, 0, s2>>>(n);
    k_scan_part<<<1, 128, 0, s2>>>(nb);
    k_apply<<<(n + 255) / 256, 256, 0, s2>>>(n, e);
    k_fill<<<(e + 255) / 256, 256, 0, s2>>>(src, dst, e);
    cudaEventRecord(evJoin, s2);

    // activation branch (default stream)
    int total4 = n * 32;
    k_x2h<<<(total4 + 255) / 256, 256>>>(x, hx, total4);
    k_prepw<<<(128 * 256 + 255) / 256, 256>>>(Ws0, Wn0, wt0, 128);
    k_prepw<<<(128 * 256 + 255) / 256, 256>>>(Ws1, Wn1, wt1, 128);
    k_prepw<<<(128 * 128 + 255) / 256, 256>>>(Ws2, Wn2, wt2, 64);

    int ga = (n + 7) / 8;
    int gm = (n + 127) / 128;

    // layer 0 GEMM (no CSR dependency)
    k_gemm<128><<<gm, 256, SM128>>>(hx, wt0, b0, ys, z, n);

    // join: combine needs CSR
    cudaStreamWaitEvent(0, evJoin, 0);

    k_comb<128, true, __half><<<ga, 256>>>(z, ys, hA, n);
    k_gemm<128><<<gm, 256, SM128>>>(hA, wt1, b1, ys, z, n);
    k_comb<128, true, __half><<<ga, 256>>>(z, ys, hx, n);
    k_gemm<64><<<gm, 256, SM64>>>(hx, wt2, b2, ys, z, n);
    k_comb<64, false, float><<<ga, 256>>>(z, ys, out, n);

    cudaEventDestroy(evFork);
    cudaEventDestroy(evJoin);
    cudaStreamDestroy(s2);
}